// round 14
// baseline (speedup 1.0000x reference)
#include <cuda_runtime.h>

// WaveFunctionDensity: rho[n,m] = sum_pq B[n,m,p] * dm[n,p,q] * B[n,m,q]
// Symmetrized block-triangular form:
//   U[p,q] = (D[p,q]+D[q,p]) * w,  w = 1 if ptile<qtile, 0.5 if ==, (0 if >)
//   rho[m] = sum_q b_q * sum_{ptile<=qtile} U[p,q] b_p      (ptile = p>>6)
//
// Kernel 1: build U into __device__ scratch (only ptile<=qtile blocks).
// Kernel 2: 512 threads (16 warps, 4/SMSP). Warps free-run over a statically
//   balanced triangular schedule in quarter-units (16 p-rows x 32 q): 288
//   units total, exactly 18 per warp, <=4 segments each. Each segment:
//   acc[16m][4q] per thread, U streamed from L2 with distance-2 prefetch,
//   own epilogue + atomicAdd (legal: rho is linear in partial acc).

#define N_MOL   16
#define MS      4096
#define NA      32
#define NP      512
#define M_TILE  64
#define THREADS 512
#define DV_LD   65

// smem (floats): sB 32768 | scratch dvT 96*65 + r2 32*64 | params 1536 | rho 64
#define SCRATCH_FLOATS (96 * DV_LD + 32 * 64)
#define SMEM_FLOATS (32768 + SCRATCH_FLOATS + 512 + 512 + 512 + 64)
#define SMEM_BYTES  (SMEM_FLOATS * 4)

// symmetrized, block-weighted density matrix (zero-init; P>Q blocks never
// written and never consumed -> deterministic)
__device__ float g_U[(size_t)N_MOL * NP * NP];

__constant__ int c_pw[20 * 3] = {
    0,0,0,
    1,0,0, 0,1,0, 0,0,1,
    2,0,0, 0,2,0, 0,0,2, 1,1,0, 1,0,1, 0,1,1,
    3,0,0, 0,3,0, 0,0,3, 2,1,0, 2,0,1, 0,2,1,
    1,2,0, 1,0,2, 0,1,2, 1,1,1
};

// Per-warp schedule: up to 4 segments of {q_col_base, quarter_start, quarter_end}.
// Columns are 32-q halves of 64-q tiles: base = qtile*64 + half*32; column
// qtile has (qtile+1)*4 p-quarters (16 rows each). 288 quarters total,
// exactly 18 per warp. base = -1 terminates.
__constant__ int c_sched[16][4][3] = {
    { {448, 0,18}, { -1,0,0}, { -1,0,0}, { -1,0,0} },
    { {448,18,32}, {480,0, 4}, { -1,0,0}, { -1,0,0} },
    { {480, 4,22}, { -1,0,0}, { -1,0,0}, { -1,0,0} },
    { {480,22,32}, {384,0, 8}, { -1,0,0}, { -1,0,0} },
    { {384, 8,26}, { -1,0,0}, { -1,0,0}, { -1,0,0} },
    { {384,26,28}, {416,0,16}, { -1,0,0}, { -1,0,0} },
    { {416,16,28}, {320,0, 6}, { -1,0,0}, { -1,0,0} },
    { {320, 6,24}, { -1,0,0}, { -1,0,0}, { -1,0,0} },
    { {352, 0,18}, { -1,0,0}, { -1,0,0}, { -1,0,0} },
    { {352,18,24}, {256,0,12}, { -1,0,0}, { -1,0,0} },
    { {256,12,20}, {288,0,10}, { -1,0,0}, { -1,0,0} },
    { {288,10,20}, {192,0, 8}, { -1,0,0}, { -1,0,0} },
    { {192, 8,16}, {224,0,10}, { -1,0,0}, { -1,0,0} },
    { {224,10,16}, {128,0,12}, { -1,0,0}, { -1,0,0} },
    { {160, 0,12}, { 64,0, 6}, { -1,0,0}, { -1,0,0} },
    { { 64, 6, 8}, { 96,0, 8}, {  0,0,4}, { 32,0,4} },
};

__device__ __forceinline__ float ipow_small(float x, int e) {
    // x^e for e in {0,1,2,3}; pow(x,0)==1 for any x (matches XLA semantics)
    float r = (e > 0 ? x : 1.0f);
    r *= (e > 1 ? x : 1.0f);
    r *= (e > 2 ? x : 1.0f);
    return r;
}

// ---- kernel 1: U = (D + D^T) with block-triangular weights ----
__global__ void build_U_kernel(const float* __restrict__ dm) {
    __shared__ float tA[32][33];
    __shared__ float tB[32][33];
    const int n  = blockIdx.z;
    const int bp = blockIdx.y * 32;
    const int bq = blockIdx.x * 32;
    const int ptile = bp >> 6, qtile = bq >> 6;
    if (ptile > qtile) return;                 // unused region stays zero

    const float* D = dm + (size_t)n * NP * NP;
    const int tx = threadIdx.x, ty0 = threadIdx.y;   // block (32, 8)
    for (int r = ty0; r < 32; r += 8) {
        tA[r][tx] = D[(size_t)(bp + r) * NP + bq + tx];
        tB[r][tx] = D[(size_t)(bq + r) * NP + bp + tx];
    }
    __syncthreads();

    const float w = (ptile == qtile) ? 0.5f : 1.0f;
    float* U = g_U + (size_t)n * NP * NP;
    for (int r = ty0; r < 32; r += 8)
        U[(size_t)(bp + r) * NP + bq + tx] = (tA[r][tx] + tB[tx][r]) * w;
}

// ---- kernel 2: fused basis + balanced free-running quadratic form ----
__global__ __launch_bounds__(THREADS, 1)
void wfn_density_kernel(const float* __restrict__ dv,
                        const int*   __restrict__ centers,
                        const float* __restrict__ exps,
                        const int*   __restrict__ syms,
                        float*       __restrict__ out) {
    extern __shared__ float smem[];
    float* sB   = smem;                          // 32768 floats
    float* dvT  = smem + 32768;                  // [96][DV_LD]
    float* r2s  = dvT + 96 * DV_LD;              // [32][64]
    float* sExp = smem + 32768 + SCRATCH_FLOATS; // 512
    int*   sCen = (int*)(sExp + 512);
    int*   sSym = sCen + 512;
    float* rhoS = (float*)(sSym + 512);          // 64

    const int tid = threadIdx.x;
    const int n   = blockIdx.y;
    const int m0  = blockIdx.x * M_TILE;

    // ---- per-primitive params ----
    for (int i = tid; i < NP; i += THREADS) {
        sExp[i] = exps[n * NP + i];
        sCen[i] = centers[n * NP + i];
        sSym[i] = syms[n * NP + i];
    }
    if (tid < M_TILE) rhoS[tid] = 0.0f;

    // ---- dv tile, transposed ----
    const float* dvsrc = dv + ((size_t)n * MS + m0) * (NA * 3);
    for (int L = tid; L < M_TILE * NA * 3; L += THREADS) {
        int mm = L / (NA * 3);
        int t  = L % (NA * 3);
        dvT[t * DV_LD + mm] = dvsrc[L];
    }
    __syncthreads();

    // ---- r2 per (atom, sample) ----
    for (int idx = tid; idx < NA * M_TILE; idx += THREADS) {
        int a = idx >> 6, mm = idx & 63;
        float x = dvT[(a * 3 + 0) * DV_LD + mm];
        float y = dvT[(a * 3 + 1) * DV_LD + mm];
        float z = dvT[(a * 3 + 2) * DV_LD + mm];
        r2s[a * 64 + mm] = x * x + y * y + z * z;
    }
    __syncthreads();

    // ---- basis tile sB[p][mm] ----
    for (int e = tid; e < NP * M_TILE; e += THREADS) {
        int p  = e >> 6;
        int mm = e & 63;
        int c  = sCen[p];
        int cc = max(c, 0);
        float alpha = sExp[p];
        int s  = sSym[p];
        int px = c_pw[s * 3 + 0], py = c_pw[s * 3 + 1], pz = c_pw[s * 3 + 2];
        float x  = dvT[(cc * 3 + 0) * DV_LD + mm];
        float y  = dvT[(cc * 3 + 1) * DV_LD + mm];
        float z  = dvT[(cc * 3 + 2) * DV_LD + mm];
        float r2 = r2s[cc * 64 + mm];
        float ang = ipow_small(x, px) * ipow_small(y, py) * ipow_small(z, pz);
        float b = ang * __expf(-alpha * r2);
        sB[p * M_TILE + mm] = (c >= 0) ? b : 0.0f;
    }
    __syncthreads();   // sB complete; warps free-run from here

    // ---- phase 2: balanced triangular segments, acc[16m][4q]/thread ----
    const float* Ug = g_U + (size_t)n * NP * NP;
    const int warp = tid >> 5;
    const int tm   = tid & 3;          // m-group: m = tm*16 + i, i in 0..15
    const int tqin = (tid >> 2) & 7;   // q-group within half-column, j in 0..3

    #pragma unroll 1
    for (int s = 0; s < 4; ++s) {
        const int base = c_sched[warp][s][0];
        if (base < 0) break;
        const int p0 = c_sched[warp][s][1] * 16;
        const int p1 = c_sched[warp][s][2] * 16;
        const int q0 = base + tqin * 4;

        float acc[16][4];
        #pragma unroll
        for (int i = 0; i < 16; ++i)
            #pragma unroll
            for (int j = 0; j < 4; ++j) acc[i][j] = 0.0f;

        const float4* Uq = (const float4*)(Ug + q0);  // row p at index p*128
        // distance-2 software pipeline over p (pairs; prefetch next pair)
        float4 uA = __ldg(&Uq[(size_t)p0 * 128]);
        float4 uB = __ldg(&Uq[(size_t)(p0 + 1) * 128]);

        for (int p = p0; p < p1; p += 2) {
            float4 cd = uA, ed = uB;
            if (p + 3 < p1) {
                uA = __ldg(&Uq[(size_t)(p + 2) * 128]);
                uB = __ldg(&Uq[(size_t)(p + 3) * 128]);
            }
            // row p
            {
                const float* brow = &sB[p * M_TILE + tm * 16];
                float4 b0 = *(const float4*)&brow[0];
                float4 b1 = *(const float4*)&brow[4];
                float4 b2 = *(const float4*)&brow[8];
                float4 b3 = *(const float4*)&brow[12];
                float bb[16] = {b0.x, b0.y, b0.z, b0.w, b1.x, b1.y, b1.z, b1.w,
                                b2.x, b2.y, b2.z, b2.w, b3.x, b3.y, b3.z, b3.w};
                float dd[4]  = {cd.x, cd.y, cd.z, cd.w};
                #pragma unroll
                for (int i = 0; i < 16; ++i)
                    #pragma unroll
                    for (int j = 0; j < 4; ++j)
                        acc[i][j] = fmaf(bb[i], dd[j], acc[i][j]);
            }
            // row p + 1
            {
                const float* brow = &sB[(p + 1) * M_TILE + tm * 16];
                float4 b0 = *(const float4*)&brow[0];
                float4 b1 = *(const float4*)&brow[4];
                float4 b2 = *(const float4*)&brow[8];
                float4 b3 = *(const float4*)&brow[12];
                float bb[16] = {b0.x, b0.y, b0.z, b0.w, b1.x, b1.y, b1.z, b1.w,
                                b2.x, b2.y, b2.z, b2.w, b3.x, b3.y, b3.z, b3.w};
                float dd[4]  = {ed.x, ed.y, ed.z, ed.w};
                #pragma unroll
                for (int i = 0; i < 16; ++i)
                    #pragma unroll
                    for (int j = 0; j < 4; ++j)
                        acc[i][j] = fmaf(bb[i], dd[j], acc[i][j]);
            }
        }

        // segment epilogue: part[i] = sum_j acc[i][j] * B[q_j, m_i]
        float part[16];
        #pragma unroll
        for (int i = 0; i < 16; ++i) part[i] = 0.0f;
        #pragma unroll
        for (int j = 0; j < 4; ++j) {
            const float* col = &sB[(q0 + j) * M_TILE + tm * 16];
            float4 c0 = *(const float4*)&col[0];
            float4 c1 = *(const float4*)&col[4];
            float4 c2 = *(const float4*)&col[8];
            float4 c3 = *(const float4*)&col[12];
            float cc[16] = {c0.x, c0.y, c0.z, c0.w, c1.x, c1.y, c1.z, c1.w,
                            c2.x, c2.y, c2.z, c2.w, c3.x, c3.y, c3.z, c3.w};
            #pragma unroll
            for (int i = 0; i < 16; ++i)
                part[i] = fmaf(acc[i][j], cc[i], part[i]);
        }
        // reduce across the 8 tqin-lanes sharing tm (lane bits 2,3,4)
        #pragma unroll
        for (int i = 0; i < 16; ++i) {
            part[i] += __shfl_xor_sync(0xFFFFFFFFu, part[i], 4);
            part[i] += __shfl_xor_sync(0xFFFFFFFFu, part[i], 8);
            part[i] += __shfl_xor_sync(0xFFFFFFFFu, part[i], 16);
        }
        if (tqin == 0) {
            #pragma unroll
            for (int i = 0; i < 16; ++i)
                atomicAdd(&rhoS[tm * 16 + i], part[i]);
        }
    }

    __syncthreads();
    if (tid < M_TILE)
        out[(size_t)n * MS + m0 + tid] = rhoS[tid];
}

extern "C" void kernel_launch(void* const* d_in, const int* in_sizes, int n_in,
                              void* d_out, int out_size) {
    const float* dv      = (const float*)d_in[0];
    const int*   centers = (const int*)  d_in[1];
    const float* exps    = (const float*)d_in[2];
    const int*   syms    = (const int*)  d_in[3];
    const float* dm      = (const float*)d_in[4];
    float* out = (float*)d_out;

    cudaFuncSetAttribute(wfn_density_kernel,
                         cudaFuncAttributeMaxDynamicSharedMemorySize, SMEM_BYTES);

    // 1) symmetrize + weight the density matrix
    dim3 ug(NP / 32, NP / 32, N_MOL);
    build_U_kernel<<<ug, dim3(32, 8)>>>(dm);

    // 2) fused density evaluation
    dim3 grid(MS / M_TILE, N_MOL);
    wfn_density_kernel<<<grid, THREADS, SMEM_BYTES>>>(dv, centers, exps, syms, out);
}

// round 17
// speedup vs baseline: 1.3065x; 1.3065x over previous
#include <cuda_runtime.h>
#include <cuda_bf16.h>
#include <cstdint>

// WaveFunctionDensity via mma.sync (HMMA, base-target PTX) bf16 split GEMM.
//   rho[n,m] = b^T D b = sum_q b_q * acc[m,q],
//   acc[m,q] = sum_{p <= (qtile+1)*64} Ut[q,p] b_p        (triangular, R11-validated)
//   Ut[q,p] = (D[p,q]+D[q,p]) * w, w = 1 (ptile<qtile), 0.5 (==), 0 (>)
//   b = bh + bl, Ut = Uh + Ul (bf16 splits); acc ~ bh*Uh + bh*Ul + bl*Uh.
//
// Kernel 1: build g_Uh/g_Ul[n][q][p] (K-major rows for the B operand).
// Kernel 2: CTA = (molecule, 64 samples), 256 thr, 8 warps = 2m x 4q grid.
//   Full basis hi/lo in smem [64m][512k] bf16 (XOR-swizzled for ldmatrix).
//   Per q-tile: k-chunks 0..qt, U tiles [64q][64k] double-buffered cp.async.
//   mma.sync.m16n8k16.row.col bf16 -> fp32; epilogue folds acc * (bh+bl)
//   into rho via shfl + smem atomics.

#define N_MOL 16
#define MS    4096
#define NA    32
#define NP    512
#define M_CTA 64
#define THREADS 256
#define DVLD  65

// smem byte offsets
#define SA_H    0        // [64][512] bf16 = 65536
#define SA_L    65536
#define SU_BASE 131072   // 2 bufs x (H 8192 + L 8192) = 32768
#define DVT_OFF 163840   // float[96][65] = 24960
#define R2S_OFF 188800   // float[32][64] = 8192
#define EXP_OFF 196992   // 512 f
#define CEN_OFF 199040   // 512 i
#define SYM_OFF 201088   // 512 i
#define RHO_OFF 203136   // 64 f
#define SMEM_TOTAL_B 203392

__device__ __nv_bfloat16 g_Uh[(size_t)N_MOL * NP * NP];
__device__ __nv_bfloat16 g_Ul[(size_t)N_MOL * NP * NP];

__constant__ int c_pw[20 * 3] = {
    0,0,0,
    1,0,0, 0,1,0, 0,0,1,
    2,0,0, 0,2,0, 0,0,2, 1,1,0, 1,0,1, 0,1,1,
    3,0,0, 0,3,0, 0,0,3, 2,1,0, 2,0,1, 0,2,1,
    1,2,0, 1,0,2, 0,1,2, 1,1,1
};

__device__ __forceinline__ float ipow_small(float x, int e) {
    float r = (e > 0 ? x : 1.0f);
    r *= (e > 1 ? x : 1.0f);
    r *= (e > 2 ? x : 1.0f);
    return r;
}

// A tile swizzle: rows of 1024B (512 bf16); XOR m%8 into 16B-chunk index.
__device__ __forceinline__ uint32_t swzA(int m, int k) {
    return (uint32_t)((m << 10) + (k << 1)) ^ (uint32_t)((m & 7) << 4);
}
// U tile swizzle: rows of 128B (64 bf16); classic SW128.
__device__ __forceinline__ uint32_t swzB(int q, int k) {
    return (uint32_t)((q << 7) + (k << 1)) ^ (uint32_t)((q & 7) << 4);
}
__device__ __forceinline__ uint32_t smem_u32(const void* p) {
    return (uint32_t)__cvta_generic_to_shared(p);
}
__device__ __forceinline__ void cp_async16(uint32_t dst, const void* src) {
    asm volatile("cp.async.cg.shared.global [%0], [%1], 16;\n" :: "r"(dst), "l"(src));
}
__device__ __forceinline__ void cp_commit() {
    asm volatile("cp.async.commit_group;\n" ::: "memory");
}
__device__ __forceinline__ void cp_wait1() {
    asm volatile("cp.async.wait_group 1;\n" ::: "memory");
}
__device__ __forceinline__ void cp_wait0() {
    asm volatile("cp.async.wait_group 0;\n" ::: "memory");
}
__device__ __forceinline__ void ldsm_x4(uint32_t* r, uint32_t addr) {
    asm volatile("ldmatrix.sync.aligned.m8n8.x4.shared.b16 {%0,%1,%2,%3}, [%4];"
        : "=r"(r[0]), "=r"(r[1]), "=r"(r[2]), "=r"(r[3]) : "r"(addr));
}
__device__ __forceinline__ void ldsm_x2(uint32_t* r, uint32_t addr) {
    asm volatile("ldmatrix.sync.aligned.m8n8.x2.shared.b16 {%0,%1}, [%2];"
        : "=r"(r[0]), "=r"(r[1]) : "r"(addr));
}
__device__ __forceinline__ void mma16816(float* d, const uint32_t* a, const uint32_t* b) {
    asm volatile("mma.sync.aligned.m16n8k16.row.col.f32.bf16.bf16.f32 "
        "{%0,%1,%2,%3}, {%4,%5,%6,%7}, {%8,%9}, {%0,%1,%2,%3};"
        : "+f"(d[0]), "+f"(d[1]), "+f"(d[2]), "+f"(d[3])
        : "r"(a[0]), "r"(a[1]), "r"(a[2]), "r"(a[3]), "r"(b[0]), "r"(b[1]));
}

// ---- kernel 1: transposed, weighted, bf16-split symmetrization ----
__global__ void build_Ut(const float* __restrict__ dm) {
    __shared__ float tA[32][33];
    __shared__ float tB[32][33];
    const int n  = blockIdx.z;
    const int p0 = blockIdx.y * 32;
    const int q0 = blockIdx.x * 32;
    const int ptile = p0 >> 6, qtile = q0 >> 6;
    if (ptile > qtile) return;                 // unused region stays zero

    const float* D = dm + (size_t)n * NP * NP;
    const int tx = threadIdx.x, ty0 = threadIdx.y;   // block (32, 8)
    for (int r = ty0; r < 32; r += 8) {
        tA[r][tx] = D[(size_t)(p0 + r) * NP + q0 + tx];
        tB[r][tx] = D[(size_t)(q0 + r) * NP + p0 + tx];
    }
    __syncthreads();
    const float w = (ptile == qtile) ? 0.5f : 1.0f;
    for (int r = ty0; r < 32; r += 8) {
        // Ut[q0+r][p0+tx] = (D[q][p] + D[p][q]) * w
        float v = (tB[r][tx] + tA[tx][r]) * w;
        __nv_bfloat16 hi = __float2bfloat16(v);
        __nv_bfloat16 lo = __float2bfloat16(v - __bfloat162float(hi));
        size_t o = ((size_t)n * NP + q0 + r) * NP + p0 + tx;
        g_Uh[o] = hi;
        g_Ul[o] = lo;
    }
}

__device__ __forceinline__ float eval_basis(const float* dvT, const float* r2s,
                                            const float* sExp, const int* sCen,
                                            const int* sSym, int m, int k) {
    int c = sCen[k];
    int cc = max(c, 0);
    float alpha = sExp[k];
    int s = sSym[k];
    int px = c_pw[s * 3 + 0], py = c_pw[s * 3 + 1], pz = c_pw[s * 3 + 2];
    float x = dvT[(cc * 3 + 0) * DVLD + m];
    float y = dvT[(cc * 3 + 1) * DVLD + m];
    float z = dvT[(cc * 3 + 2) * DVLD + m];
    float r2 = r2s[cc * 64 + m];
    float ang = ipow_small(x, px) * ipow_small(y, py) * ipow_small(z, pz);
    float b = ang * __expf(-alpha * r2);
    return (c >= 0) ? b : 0.0f;
}

// ---- helper: issue cp.async for one U chunk (qt, kc) into buffer buf ----
__device__ __forceinline__ void load_chunk(char* smem, uint32_t sbase, int n,
                                           int qt, int kc, int buf, int tid) {
    const char* baseH = (const char*)g_Uh +
        ((size_t)(n * NP + qt * 64) * NP + kc * 64) * 2;
    const char* baseL = (const char*)g_Ul +
        ((size_t)(n * NP + qt * 64) * NP + kc * 64) * 2;
    const uint32_t dH = sbase + SU_BASE + buf * 16384;
    const uint32_t dL = dH + 8192;
    for (int v = tid; v < 64 * 8; v += THREADS) {
        int r = v >> 3, seg = v & 7;
        uint32_t off = swzB(r, seg * 8);          // seg*16 bytes = k of seg*8
        cp_async16(dH + off, baseH + (size_t)r * (NP * 2) + seg * 16);
        cp_async16(dL + off, baseL + (size_t)r * (NP * 2) + seg * 16);
    }
}

// ---- kernel 2: fused basis + HMMA triangular quadratic form ----
__global__ __launch_bounds__(THREADS, 1)
void wfn_density_mma(const float* __restrict__ dv,
                     const int*   __restrict__ centers,
                     const float* __restrict__ exps,
                     const int*   __restrict__ syms,
                     float*       __restrict__ out) {
    extern __shared__ char smem[];
    float* dvT  = (float*)(smem + DVT_OFF);
    float* r2s  = (float*)(smem + R2S_OFF);
    float* sExp = (float*)(smem + EXP_OFF);
    int*   sCen = (int*)  (smem + CEN_OFF);
    int*   sSym = (int*)  (smem + SYM_OFF);
    float* rhoS = (float*)(smem + RHO_OFF);

    const int tid  = threadIdx.x;
    const int lane = tid & 31;
    const int warp = tid >> 5;
    const int warp_m = warp >> 2;      // 0..1 -> 32 m rows each
    const int warp_q = warp & 3;       // 0..3 -> 16 q cols each
    const int n   = blockIdx.y;
    const int m0  = blockIdx.x * M_CTA;
    const uint32_t sbase = smem_u32(smem);

    // prologue prefetch: chunk (qt=0, kc=0) into buf 0 (overlaps basis gen)
    load_chunk(smem, sbase, n, 0, 0, 0, tid);
    cp_commit();

    // ---- params ----
    for (int i = tid; i < NP; i += THREADS) {
        sExp[i] = exps[n * NP + i];
        sCen[i] = centers[n * NP + i];
        sSym[i] = syms[n * NP + i];
    }
    if (tid < M_CTA) rhoS[tid] = 0.0f;

    // ---- dv tile transposed ----
    const float* dvsrc = dv + ((size_t)n * MS + m0) * (NA * 3);
    for (int L = tid; L < M_CTA * NA * 3; L += THREADS) {
        int mm = L / (NA * 3);
        int t  = L % (NA * 3);
        dvT[t * DVLD + mm] = dvsrc[L];
    }
    __syncthreads();
    for (int idx = tid; idx < NA * M_CTA; idx += THREADS) {
        int a = idx >> 6, mm = idx & 63;
        float x = dvT[(a * 3 + 0) * DVLD + mm];
        float y = dvT[(a * 3 + 1) * DVLD + mm];
        float z = dvT[(a * 3 + 2) * DVLD + mm];
        r2s[a * 64 + mm] = x * x + y * y + z * z;
    }
    __syncthreads();

    // ---- full basis tile, hi/lo split, swizzled ----
    for (int v = tid; v < M_CTA * 256; v += THREADS) {
        int m = v >> 8;
        int k = (v & 255) * 2;
        float b0 = eval_basis(dvT, r2s, sExp, sCen, sSym, m, k);
        float b1 = eval_basis(dvT, r2s, sExp, sCen, sSym, m, k + 1);
        __nv_bfloat16 h0 = __float2bfloat16(b0);
        __nv_bfloat16 h1 = __float2bfloat16(b1);
        __nv_bfloat16 l0 = __float2bfloat16(b0 - __bfloat162float(h0));
        __nv_bfloat16 l1 = __float2bfloat16(b1 - __bfloat162float(h1));
        uint32_t off = swzA(m, k);
        __nv_bfloat162 vh; vh.x = h0; vh.y = h1;
        __nv_bfloat162 vl; vl.x = l0; vl.y = l1;
        *(__nv_bfloat162*)(smem + SA_H + off) = vh;
        *(__nv_bfloat162*)(smem + SA_L + off) = vl;
    }
    __syncthreads();

    // ---- mainloop over q-tiles, triangular k-chunks ----
    // ldmatrix lane addressing (constant per thread):
    const int a_row  = warp_m * 32 + (lane & 15);  // + mt*16
    const int a_koff = (lane & 16) >> 1;           // 0 or 8
    const int b_rowl = (lane & 7);                 // + warp_q*16 + nt*8
    const int b_koff = (lane & 8);                 // 0 or 8

    int buf = 0;
    for (int qt = 0; qt < 8; ++qt) {
        float acc[2][2][4];
        #pragma unroll
        for (int mt = 0; mt < 2; ++mt)
            #pragma unroll
            for (int nt = 0; nt < 2; ++nt)
                #pragma unroll
                for (int r = 0; r < 4; ++r) acc[mt][nt][r] = 0.0f;

        for (int kc = 0; kc <= qt; ++kc) {
            // prefetch next chunk
            if (!(qt == 7 && kc == qt)) {
                int nqt = (kc < qt) ? qt : qt + 1;
                int nkc = (kc < qt) ? kc + 1 : 0;
                load_chunk(smem, sbase, n, nqt, nkc, buf ^ 1, tid);
                cp_commit();
                cp_wait1();
            } else {
                cp_wait0();
            }
            __syncthreads();

            const uint32_t uH = sbase + SU_BASE + buf * 16384;
            const uint32_t uL = uH + 8192;
            const int kb = kc * 64;

            #pragma unroll
            for (int ks = 0; ks < 4; ++ks) {
                const int kkA = kb + ks * 16 + a_koff;   // global k for A
                const int kkB = ks * 16 + b_koff;        // local k in U tile
                uint32_t ah[2][4], al[2][4];
                #pragma unroll
                for (int mt = 0; mt < 2; ++mt) {
                    uint32_t offm = swzA(a_row + mt * 16, kkA);
                    ldsm_x4(ah[mt], sbase + SA_H + offm);
                    ldsm_x4(al[mt], sbase + SA_L + offm);
                }
                uint32_t bh[2][2], bl[2][2];
                #pragma unroll
                for (int nt = 0; nt < 2; ++nt) {
                    uint32_t offq = swzB(warp_q * 16 + nt * 8 + b_rowl, kkB);
                    ldsm_x2(bh[nt], uH + offq);
                    ldsm_x2(bl[nt], uL + offq);
                }
                #pragma unroll
                for (int mt = 0; mt < 2; ++mt)
                    #pragma unroll
                    for (int nt = 0; nt < 2; ++nt) {
                        mma16816(acc[mt][nt], ah[mt], bh[nt]);
                        mma16816(acc[mt][nt], ah[mt], bl[nt]);
                        mma16816(acc[mt][nt], al[mt], bh[nt]);
                    }
            }
            __syncthreads();   // all warps done with buf before it's refilled
            buf ^= 1;
        }

        // ---- q-tile epilogue: rho[m] += sum_q acc[m,q] * (bh+bl)[m,q] ----
        float pm[4] = {0.0f, 0.0f, 0.0f, 0.0f};
        #pragma unroll
        for (int mt = 0; mt < 2; ++mt)
            #pragma unroll
            for (int nt = 0; nt < 2; ++nt)
                #pragma unroll
                for (int h = 0; h < 2; ++h)
                    #pragma unroll
                    for (int c = 0; c < 2; ++c) {
                        int m = warp_m * 32 + mt * 16 + (lane >> 2) + h * 8;
                        int q = qt * 64 + warp_q * 16 + nt * 8 + (lane & 3) * 2 + c;
                        uint32_t off = swzA(m, q);
                        float b = __bfloat162float(*(__nv_bfloat16*)(smem + SA_H + off))
                                + __bfloat162float(*(__nv_bfloat16*)(smem + SA_L + off));
                        pm[mt * 2 + h] = fmaf(acc[mt][nt][h * 2 + c], b, pm[mt * 2 + h]);
                    }
        #pragma unroll
        for (int i = 0; i < 4; ++i) {
            pm[i] += __shfl_xor_sync(0xFFFFFFFFu, pm[i], 1);
            pm[i] += __shfl_xor_sync(0xFFFFFFFFu, pm[i], 2);
        }
        if ((lane & 3) == 0) {
            #pragma unroll
            for (int mt = 0; mt < 2; ++mt)
                #pragma unroll
                for (int h = 0; h < 2; ++h)
                    atomicAdd(&rhoS[warp_m * 32 + mt * 16 + (lane >> 2) + h * 8],
                              pm[mt * 2 + h]);
        }
    }

    __syncthreads();
    if (tid < M_CTA)
        out[(size_t)n * MS + m0 + tid] = rhoS[tid];
}

extern "C" void kernel_launch(void* const* d_in, const int* in_sizes, int n_in,
                              void* d_out, int out_size) {
    const float* dv      = (const float*)d_in[0];
    const int*   centers = (const int*)  d_in[1];
    const float* exps    = (const float*)d_in[2];
    const int*   syms    = (const int*)  d_in[3];
    const float* dm      = (const float*)d_in[4];
    float* out = (float*)d_out;

    cudaFuncSetAttribute(wfn_density_mma,
                         cudaFuncAttributeMaxDynamicSharedMemorySize, SMEM_TOTAL_B);

    // 1) transposed symmetrize + triangular weights + bf16 split
    dim3 sg(NP / 32, NP / 32, N_MOL);
    build_Ut<<<sg, dim3(32, 8)>>>(dm);

    // 2) fused density evaluation (HMMA tensor cores)
    dim3 grid(MS / M_CTA, N_MOL);
    wfn_density_mma<<<grid, THREADS, SMEM_TOTAL_B>>>(dv, centers, exps, syms, out);
}